// round 13
// baseline (speedup 1.0000x reference)
#include <cuda_runtime.h>
#include <cuda_fp16.h>
#include <cstdint>

#define T_DIM 2048
#define B_DIM 8
#define D_DIM 1024
#define C_DIM 8192              // B*D channels
#define M_DIM 16384             // T*B gemm rows
#define N_DIM 2048              // alpha|v concat
#define K_DIM 1024

#define SEG 32
#define SLEN 64                 // T / SEG

// ---------------- device scratch ----------------
__device__ unsigned short g_a16[(size_t)M_DIM * D_DIM];  // alpha, u16 fixed (a*65536)
__device__ unsigned short g_v16[(size_t)M_DIM * D_DIM];  // v, fp16 bits
__device__ __half g_xh[(size_t)M_DIM * K_DIM];
__device__ __half g_w[(size_t)N_DIM * K_DIM];
__device__ float g_P[SEG * C_DIM];
__device__ float g_Q[SEG * C_DIM];

// ---------------- helpers ----------------
__device__ __forceinline__ uint32_t smem_u32(const void* p) {
    uint32_t a;
    asm("{ .reg .u64 t; cvta.to.shared.u64 t, %1; cvt.u32.u64 %0, t; }" : "=r"(a) : "l"(p));
    return a;
}

__device__ __forceinline__ float fast_sigmoid(float z) {
    return __fdividef(1.0f, 1.0f + __expf(-z));
}

#define LDSM4(r, addr) \
    asm volatile("ldmatrix.sync.aligned.m8n8.x4.shared.b16 {%0,%1,%2,%3}, [%4];" \
        : "=r"((r)[0]), "=r"((r)[1]), "=r"((r)[2]), "=r"((r)[3]) : "r"(addr))

#define MMA16816(c, a, b0, b1) \
    asm volatile("mma.sync.aligned.m16n8k16.row.col.f32.f16.f16.f32 " \
        "{%0,%1,%2,%3}, {%4,%5,%6,%7}, {%8,%9}, {%0,%1,%2,%3};" \
        : "+f"((c)[0]), "+f"((c)[1]), "+f"((c)[2]), "+f"((c)[3]) \
        : "r"((a)[0]), "r"((a)[1]), "r"((a)[2]), "r"((a)[3]), "r"(b0), "r"(b1))

// ---------------- merged convert kernel (f32 -> fp16) ----------------
#define XB ((M_DIM * K_DIM) / 1024)          // 16384
#define WB ((N_DIM * K_DIM) / 1024)          // 2048

__global__ __launch_bounds__(256) void conv_all_kernel(const float* __restrict__ x,
                                                       const float* __restrict__ Wa,
                                                       const float* __restrict__ Wv) {
    if (blockIdx.x < XB) {
        size_t i = ((size_t)blockIdx.x * 256 + threadIdx.x) * 4;
        float4 f = *(const float4*)(x + i);
        __half2* H = (__half2*)(g_xh + i);
        H[0] = __halves2half2(__float2half_rn(f.x), __float2half_rn(f.y));
        H[1] = __halves2half2(__float2half_rn(f.z), __float2half_rn(f.w));
    } else {
        size_t i = ((size_t)(blockIdx.x - XB) * 256 + threadIdx.x) * 4;
        size_t n = i >> 10;
        const float* src = (n < D_DIM) ? (Wa + i) : (Wv + (i - (size_t)D_DIM * K_DIM));
        float4 f = *(const float4*)src;
        __half2* H = (__half2*)(g_w + i);
        H[0] = __halves2half2(__float2half_rn(f.x), __float2half_rn(f.y));
        H[1] = __halves2half2(__float2half_rn(f.z), __float2half_rn(f.w));
    }
}

// ---------------- HMMA GEMM ----------------
// C[m,n] = x*W (fp16 inputs, fp32 accum), single pass.
// BM=128, BN=128, BK=32, 256 threads (8 warps, 64x32 warp tiles), 3-stage cp.async.
// Proven config: 2 CTAs/SM is load-bearing — do not grow CTA/smem/warp-tile.
#define BK 32
#define NKK 32                       // 1024/32
#define ASTG (128 * BK * 2)          // 8192 B
#define STAGE_BYTES (2 * ASTG)       // A + B = 16384 B
#define GSMEM (3 * STAGE_BYTES + 128)

// smem chunk index (16B units) with xor swizzle for conflict-free LDSM
__device__ __forceinline__ uint32_t chunk_off(int r, int kb) {
    return (uint32_t)((r * 4 + (kb ^ ((r >> 1) & 3))) * 16);
}

__device__ __forceinline__ void load_stage(uint32_t smBase, int slot,
                                           const __half* Asrc,
                                           const __half* Bsrc, int tid) {
    uint32_t sA = smBase + (uint32_t)slot * STAGE_BYTES;
    uint32_t sB = sA + ASTG;
#pragma unroll
    for (int j = 0; j < 2; ++j) {
        int idx = tid + j * 256;
        int r = idx >> 2, cb = idx & 3;
        const char* gp = (const char*)(Asrc + (size_t)r * K_DIM) + cb * 16;
        asm volatile("cp.async.cg.shared.global [%0], [%1], 16;"
                     :: "r"(sA + chunk_off(r, cb)), "l"(gp));
    }
#pragma unroll
    for (int j = 0; j < 2; ++j) {
        int idx = tid + j * 256;
        int r = idx >> 2, cb = idx & 3;
        const char* gp = (const char*)(Bsrc + (size_t)r * K_DIM) + cb * 16;
        asm volatile("cp.async.cg.shared.global [%0], [%1], 16;"
                     :: "r"(sB + chunk_off(r, cb)), "l"(gp));
    }
    asm volatile("cp.async.commit_group;" ::: "memory");
}

__global__ __launch_bounds__(256, 2)
void gemm_hmma_kernel(const float* __restrict__ b_alpha, const float* __restrict__ b_v) {
    extern __shared__ char smem[];
    uint32_t smBase = (smem_u32(smem) + 127u) & ~127u;

    const int tid = threadIdx.x;
    const int l = tid & 31, wid = tid >> 5;
    const int warpM = (wid & 1) * 64;
    const int warpN = (wid >> 1) * 32;
    const int mBase = blockIdx.y * 128;
    const int nBase = blockIdx.x * 128;
    const bool isA = (nBase < D_DIM);
    const int ncol0 = isA ? nBase : (nBase - D_DIM);

    const __half* Ax = g_xh + (size_t)mBase * K_DIM;
    const __half* Bw = g_w + (size_t)nBase * K_DIM;

    float acc[4][4][4];
#pragma unroll
    for (int i = 0; i < 4; ++i)
#pragma unroll
        for (int j = 0; j < 4; ++j)
#pragma unroll
            for (int q = 0; q < 4; ++q) acc[i][j][q] = 0.0f;

    // per-lane ldmatrix params: lane group g -> (row +8*(g&1), kblk + (g>>1))
    const int g = l >> 3, rw = l & 7;
    uint32_t rowAoff[4], swA[4];
#pragma unroll
    for (int mf = 0; mf < 4; ++mf) {
        int r = warpM + mf * 16 + (g & 1) * 8 + rw;
        rowAoff[mf] = (uint32_t)r * 64;        // r*4 chunks * 16B
        swA[mf] = (uint32_t)((r >> 1) & 3);
    }
    uint32_t rowBoff[2], swB[2];
#pragma unroll
    for (int p = 0; p < 2; ++p) {
        int r = warpN + p * 16 + (g & 1) * 8 + rw;
        rowBoff[p] = (uint32_t)r * 64;
        swB[p] = (uint32_t)((r >> 1) & 3);
    }
    const int kb_g = g >> 1;

    load_stage(smBase, 0, Ax, Bw, tid);
    load_stage(smBase, 1, Ax + 32, Bw + 32, tid);

    for (int kk = 0; kk < NKK; ++kk) {
        const int slot = kk % 3;
        if (kk < NKK - 1) asm volatile("cp.async.wait_group 1;" ::: "memory");
        else              asm volatile("cp.async.wait_group 0;" ::: "memory");
        __syncthreads();

        const int kn = kk + 2;
        if (kn < NKK) {
            const int ko = kn * 32;
            load_stage(smBase, kn % 3, Ax + ko, Bw + ko, tid);
        }

        const uint32_t sA = smBase + (uint32_t)slot * STAGE_BYTES;
        const uint32_t sB = sA + ASTG;
#pragma unroll
        for (int h = 0; h < 2; ++h) {
            const uint32_t kb = (uint32_t)(h * 2 + kb_g);
            uint32_t a[4][4], b[2][4];
#pragma unroll
            for (int mf = 0; mf < 4; ++mf)
                LDSM4(a[mf], sA + rowAoff[mf] + ((kb ^ swA[mf]) << 4));
#pragma unroll
            for (int p = 0; p < 2; ++p)
                LDSM4(b[p], sB + rowBoff[p] + ((kb ^ swB[p]) << 4));
#pragma unroll
            for (int mf = 0; mf < 4; ++mf)
#pragma unroll
                for (int nf = 0; nf < 4; ++nf) {
                    const int p = nf >> 1, sub = nf & 1;
                    MMA16816(acc[mf][nf], a[mf], b[p][sub], b[p][sub + 2]);
                }
        }
    }

    // epilogue: bias; alpha -> sigmoid -> u16 fixed (g_a16); v -> fp16 (g_v16).
    const float* __restrict__ bias = isA ? b_alpha : b_v;
    unsigned short* __restrict__ dst = isA ? g_a16 : g_v16;

    float bvv[4][2];
#pragma unroll
    for (int nf = 0; nf < 4; ++nf) {
        const int c = ncol0 + warpN + nf * 8 + (l & 3) * 2;
        bvv[nf][0] = bias[c];
        bvv[nf][1] = bias[c + 1];
    }

#pragma unroll
    for (int mf = 0; mf < 4; ++mf) {
        const int r0 = mBase + warpM + mf * 16 + (l >> 2);
#pragma unroll
        for (int hh = 0; hh < 2; ++hh) {
            const size_t mrow = (size_t)(r0 + hh * 8) * D_DIM;
#pragma unroll
            for (int nf = 0; nf < 4; ++nf) {
                const int e = ncol0 + warpN + nf * 8 + (l & 3) * 2;
                float v0 = acc[mf][nf][hh * 2 + 0] + bvv[nf][0];
                float v1 = acc[mf][nf][hh * 2 + 1] + bvv[nf][1];
                unsigned short s0, s1;
                if (isA) {
                    unsigned u0 = __float2uint_rn(fast_sigmoid(v0) * 65536.0f);
                    unsigned u1 = __float2uint_rn(fast_sigmoid(v1) * 65536.0f);
                    s0 = (unsigned short)(u0 > 65535u ? 65535u : u0);
                    s1 = (unsigned short)(u1 > 65535u ? 65535u : u1);
                } else {
                    s0 = __half_as_ushort(__float2half_rn(v0));
                    s1 = __half_as_ushort(__float2half_rn(v1));
                }
                ushort2 st; st.x = s0; st.y = s1;
                *(ushort2*)(dst + mrow + e) = st;
            }
        }
    }
}

// ---------------- segmented scan ----------------
__global__ __launch_bounds__(256) void scan_pass1_kernel() {
    const int idx = blockIdx.x * 256 + threadIdx.x;      // seg*C + ch
    const int ch = idx & (C_DIM - 1);
    const int s = idx >> 13;
    const size_t off = (size_t)s * SLEN * C_DIM + ch;
    const unsigned short* __restrict__ A = g_a16 + off;
    const unsigned short* __restrict__ V = g_v16 + off;
    float P = 1.0f, Q = 0.0f;
#pragma unroll 8
    for (int i = 0; i < SLEN; ++i) {
        float a = (float)A[(size_t)i * C_DIM] * 1.52587890625e-5f;
        float v = __half2float(__ushort_as_half(V[(size_t)i * C_DIM]));
        P *= a;
        Q = fmaf(a, Q - v, v);
    }
    g_P[idx] = P;
    g_Q[idx] = Q;
}

// pass2 computes its own segment-start h from h0 + prefix chain over (P,Q).
__global__ __launch_bounds__(256) void scan_pass2_kernel(const float* __restrict__ h0,
                                                         float* __restrict__ out,
                                                         float* __restrict__ hs, int write_h) {
    const int idx = blockIdx.x * 256 + threadIdx.x;
    const int ch = idx & (C_DIM - 1);
    const int s = idx >> 13;                 // uniform per block
    float h = h0[ch];
    for (int k = 0; k < s; ++k)              // prefix chain (coalesced, short)
        h = fmaf(g_P[k * C_DIM + ch], h, g_Q[k * C_DIM + ch]);
    if (write_h && s == 0) hs[ch] = h0[ch];  // h[0] row

    const size_t base = (size_t)s * SLEN * C_DIM + ch;
    const unsigned short* __restrict__ A = g_a16 + base;
    const unsigned short* __restrict__ V = g_v16 + base;
#pragma unroll 8
    for (int i = 0; i < SLEN; ++i) {
        float a = (float)A[(size_t)i * C_DIM] * 1.52587890625e-5f;
        float v = __half2float(__ushort_as_half(V[(size_t)i * C_DIM]));
        h = fmaf(a, h - v, v);
        float sil = __fdividef(h, 1.0f + __expf(-h));   // silu(h)
        out[base + (size_t)i * C_DIM] = h * sil;
        if (write_h) hs[base + (size_t)(i + 1) * C_DIM] = h;
    }
}

// ---------------- launch ----------------
extern "C" void kernel_launch(void* const* d_in, const int* in_sizes, int n_in,
                              void* d_out, int out_size) {
    const float* x  = (const float*)d_in[0];
    const float* h0 = (const float*)d_in[1];
    const float* Wa = (const float*)d_in[2];
    const float* ba = (const float*)d_in[3];
    const float* Wv = (const float*)d_in[4];
    const float* bv = (const float*)d_in[5];

    float* out = (float*)d_out;
    const long long out_elems = (long long)T_DIM * C_DIM;
    const long long h_elems = (long long)(T_DIM + 1) * C_DIM;
    const int write_h = (out_size >= (long long)(out_elems + h_elems)) ? 1 : 0;
    float* hs = out + out_elems;

    conv_all_kernel<<<XB + WB, 256>>>(x, Wa, Wv);

    static int configured = 0;
    if (!configured) {
        cudaFuncSetAttribute(gemm_hmma_kernel,
                             cudaFuncAttributeMaxDynamicSharedMemorySize, GSMEM);
        cudaFuncSetAttribute(gemm_hmma_kernel,
                             cudaFuncAttributePreferredSharedMemoryCarveout,
                             cudaSharedmemCarveoutMaxShared);
        configured = 1;
    }
    gemm_hmma_kernel<<<dim3(N_DIM / 128, M_DIM / 128), 256, GSMEM>>>(ba, bv);

    scan_pass1_kernel<<<(SEG * C_DIM) / 256, 256>>>();
    scan_pass2_kernel<<<(SEG * C_DIM) / 256, 256>>>(h0, out, hs, write_h);
}

// round 14
// speedup vs baseline: 1.4469x; 1.4469x over previous
#include <cuda_runtime.h>
#include <cuda_fp16.h>
#include <cstdint>

#define T_DIM 2048
#define B_DIM 8
#define D_DIM 1024
#define C_DIM 8192              // B*D channels
#define M_DIM 16384             // T*B gemm rows
#define N_DIM 2048              // alpha|v concat
#define K_DIM 1024

#define SEG 32
#define SLEN 64                 // T / SEG

// ---------------- device scratch ----------------
__device__ unsigned short g_a16[(size_t)M_DIM * D_DIM];  // alpha, u16 fixed (a*65536)
__device__ unsigned short g_v16[(size_t)M_DIM * D_DIM];  // v, fp16 bits
__device__ __half g_xh[(size_t)M_DIM * K_DIM];
__device__ __half g_w[(size_t)N_DIM * K_DIM];
__device__ float g_P[SEG * C_DIM];
__device__ float g_Q[SEG * C_DIM];

// ---------------- helpers ----------------
__device__ __forceinline__ uint32_t smem_u32(const void* p) {
    uint32_t a;
    asm("{ .reg .u64 t; cvta.to.shared.u64 t, %1; cvt.u32.u64 %0, t; }" : "=r"(a) : "l"(p));
    return a;
}

__device__ __forceinline__ float fast_sigmoid(float z) {
    return __fdividef(1.0f, 1.0f + __expf(-z));
}

#define LDSM4(r, addr) \
    asm volatile("ldmatrix.sync.aligned.m8n8.x4.shared.b16 {%0,%1,%2,%3}, [%4];" \
        : "=r"((r)[0]), "=r"((r)[1]), "=r"((r)[2]), "=r"((r)[3]) : "r"(addr))

#define MMA16816(c, a, b0, b1) \
    asm volatile("mma.sync.aligned.m16n8k16.row.col.f32.f16.f16.f32 " \
        "{%0,%1,%2,%3}, {%4,%5,%6,%7}, {%8,%9}, {%0,%1,%2,%3};" \
        : "+f"((c)[0]), "+f"((c)[1]), "+f"((c)[2]), "+f"((c)[3]) \
        : "r"((a)[0]), "r"((a)[1]), "r"((a)[2]), "r"((a)[3]), "r"(b0), "r"(b1))

// ---------------- merged convert kernel (f32 -> fp16) ----------------
#define XB ((M_DIM * K_DIM) / 1024)          // 16384
#define WB ((N_DIM * K_DIM) / 1024)          // 2048

__global__ __launch_bounds__(256) void conv_all_kernel(const float* __restrict__ x,
                                                       const float* __restrict__ Wa,
                                                       const float* __restrict__ Wv) {
    if (blockIdx.x < XB) {
        size_t i = ((size_t)blockIdx.x * 256 + threadIdx.x) * 4;
        float4 f = *(const float4*)(x + i);
        __half2* H = (__half2*)(g_xh + i);
        H[0] = __halves2half2(__float2half_rn(f.x), __float2half_rn(f.y));
        H[1] = __halves2half2(__float2half_rn(f.z), __float2half_rn(f.w));
    } else {
        size_t i = ((size_t)(blockIdx.x - XB) * 256 + threadIdx.x) * 4;
        size_t n = i >> 10;
        const float* src = (n < D_DIM) ? (Wa + i) : (Wv + (i - (size_t)D_DIM * K_DIM));
        float4 f = *(const float4*)src;
        __half2* H = (__half2*)(g_w + i);
        H[0] = __halves2half2(__float2half_rn(f.x), __float2half_rn(f.y));
        H[1] = __halves2half2(__float2half_rn(f.z), __float2half_rn(f.w));
    }
}

// ---------------- HMMA GEMM ----------------
// C[m,n] = x*W (fp16 inputs, fp32 accum), single pass.
// BM=128, BN=128, BK=32, 256 threads (8 warps, 64x32 warp tiles), 3-stage cp.async.
// Proven config: 2 CTAs/SM is load-bearing — do not grow CTA/smem/warp-tile.
#define BK 32
#define NKK 32                       // 1024/32
#define ASTG (128 * BK * 2)          // 8192 B
#define STAGE_BYTES (2 * ASTG)       // A + B = 16384 B
#define GSMEM (3 * STAGE_BYTES + 128)

// smem chunk index (16B units) with xor swizzle for conflict-free LDSM
__device__ __forceinline__ uint32_t chunk_off(int r, int kb) {
    return (uint32_t)((r * 4 + (kb ^ ((r >> 1) & 3))) * 16);
}

__device__ __forceinline__ void load_stage(uint32_t smBase, int slot,
                                           const __half* Asrc,
                                           const __half* Bsrc, int tid) {
    uint32_t sA = smBase + (uint32_t)slot * STAGE_BYTES;
    uint32_t sB = sA + ASTG;
#pragma unroll
    for (int j = 0; j < 2; ++j) {
        int idx = tid + j * 256;
        int r = idx >> 2, cb = idx & 3;
        const char* gp = (const char*)(Asrc + (size_t)r * K_DIM) + cb * 16;
        asm volatile("cp.async.cg.shared.global [%0], [%1], 16;"
                     :: "r"(sA + chunk_off(r, cb)), "l"(gp));
    }
#pragma unroll
    for (int j = 0; j < 2; ++j) {
        int idx = tid + j * 256;
        int r = idx >> 2, cb = idx & 3;
        const char* gp = (const char*)(Bsrc + (size_t)r * K_DIM) + cb * 16;
        asm volatile("cp.async.cg.shared.global [%0], [%1], 16;"
                     :: "r"(sB + chunk_off(r, cb)), "l"(gp));
    }
    asm volatile("cp.async.commit_group;" ::: "memory");
}

__global__ __launch_bounds__(256, 2)
void gemm_hmma_kernel(const float* __restrict__ b_alpha, const float* __restrict__ b_v) {
    extern __shared__ char smem[];
    uint32_t smBase = (smem_u32(smem) + 127u) & ~127u;

    const int tid = threadIdx.x;
    const int l = tid & 31, wid = tid >> 5;
    const int warpM = (wid & 1) * 64;
    const int warpN = (wid >> 1) * 32;
    const int mBase = blockIdx.y * 128;
    const int nBase = blockIdx.x * 128;
    const bool isA = (nBase < D_DIM);
    const int ncol0 = isA ? nBase : (nBase - D_DIM);

    const __half* Ax = g_xh + (size_t)mBase * K_DIM;
    const __half* Bw = g_w + (size_t)nBase * K_DIM;

    float acc[4][4][4];
#pragma unroll
    for (int i = 0; i < 4; ++i)
#pragma unroll
        for (int j = 0; j < 4; ++j)
#pragma unroll
            for (int q = 0; q < 4; ++q) acc[i][j][q] = 0.0f;

    // per-lane ldmatrix params: lane group g -> (row +8*(g&1), kblk + (g>>1))
    const int g = l >> 3, rw = l & 7;
    uint32_t rowAoff[4], swA[4];
#pragma unroll
    for (int mf = 0; mf < 4; ++mf) {
        int r = warpM + mf * 16 + (g & 1) * 8 + rw;
        rowAoff[mf] = (uint32_t)r * 64;        // r*4 chunks * 16B
        swA[mf] = (uint32_t)((r >> 1) & 3);
    }
    uint32_t rowBoff[2], swB[2];
#pragma unroll
    for (int p = 0; p < 2; ++p) {
        int r = warpN + p * 16 + (g & 1) * 8 + rw;
        rowBoff[p] = (uint32_t)r * 64;
        swB[p] = (uint32_t)((r >> 1) & 3);
    }
    const int kb_g = g >> 1;

    load_stage(smBase, 0, Ax, Bw, tid);
    load_stage(smBase, 1, Ax + 32, Bw + 32, tid);

    for (int kk = 0; kk < NKK; ++kk) {
        const int slot = kk % 3;
        if (kk < NKK - 1) asm volatile("cp.async.wait_group 1;" ::: "memory");
        else              asm volatile("cp.async.wait_group 0;" ::: "memory");
        __syncthreads();

        const int kn = kk + 2;
        if (kn < NKK) {
            const int ko = kn * 32;
            load_stage(smBase, kn % 3, Ax + ko, Bw + ko, tid);
        }

        const uint32_t sA = smBase + (uint32_t)slot * STAGE_BYTES;
        const uint32_t sB = sA + ASTG;
#pragma unroll
        for (int h = 0; h < 2; ++h) {
            const uint32_t kb = (uint32_t)(h * 2 + kb_g);
            uint32_t a[4][4], b[2][4];
#pragma unroll
            for (int mf = 0; mf < 4; ++mf)
                LDSM4(a[mf], sA + rowAoff[mf] + ((kb ^ swA[mf]) << 4));
#pragma unroll
            for (int p = 0; p < 2; ++p)
                LDSM4(b[p], sB + rowBoff[p] + ((kb ^ swB[p]) << 4));
#pragma unroll
            for (int mf = 0; mf < 4; ++mf)
#pragma unroll
                for (int nf = 0; nf < 4; ++nf) {
                    const int p = nf >> 1, sub = nf & 1;
                    MMA16816(acc[mf][nf], a[mf], b[p][sub], b[p][sub + 2]);
                }
        }
    }

    // epilogue: bias; alpha -> sigmoid -> u16 fixed (g_a16); v -> fp16 (g_v16).
    const float* __restrict__ bias = isA ? b_alpha : b_v;
    unsigned short* __restrict__ dst = isA ? g_a16 : g_v16;

    float bvv[4][2];
#pragma unroll
    for (int nf = 0; nf < 4; ++nf) {
        const int c = ncol0 + warpN + nf * 8 + (l & 3) * 2;
        bvv[nf][0] = bias[c];
        bvv[nf][1] = bias[c + 1];
    }

#pragma unroll
    for (int mf = 0; mf < 4; ++mf) {
        const int r0 = mBase + warpM + mf * 16 + (l >> 2);
#pragma unroll
        for (int hh = 0; hh < 2; ++hh) {
            const size_t mrow = (size_t)(r0 + hh * 8) * D_DIM;
#pragma unroll
            for (int nf = 0; nf < 4; ++nf) {
                const int e = ncol0 + warpN + nf * 8 + (l & 3) * 2;
                float v0 = acc[mf][nf][hh * 2 + 0] + bvv[nf][0];
                float v1 = acc[mf][nf][hh * 2 + 1] + bvv[nf][1];
                unsigned short s0, s1;
                if (isA) {
                    unsigned u0 = __float2uint_rn(fast_sigmoid(v0) * 65536.0f);
                    unsigned u1 = __float2uint_rn(fast_sigmoid(v1) * 65536.0f);
                    s0 = (unsigned short)(u0 > 65535u ? 65535u : u0);
                    s1 = (unsigned short)(u1 > 65535u ? 65535u : u1);
                } else {
                    s0 = __half_as_ushort(__float2half_rn(v0));
                    s1 = __half_as_ushort(__float2half_rn(v1));
                }
                ushort2 st; st.x = s0; st.y = s1;
                *(ushort2*)(dst + mrow + e) = st;
            }
        }
    }
}

// ---------------- segmented scan ----------------
__global__ __launch_bounds__(256) void scan_pass1_kernel() {
    const int idx = blockIdx.x * 256 + threadIdx.x;      // seg*C + ch
    const int ch = idx & (C_DIM - 1);
    const int s = idx >> 13;
    const size_t off = (size_t)s * SLEN * C_DIM + ch;
    const unsigned short* __restrict__ A = g_a16 + off;
    const unsigned short* __restrict__ V = g_v16 + off;
    float P = 1.0f, Q = 0.0f;
#pragma unroll 8
    for (int i = 0; i < SLEN; ++i) {
        float a = (float)A[(size_t)i * C_DIM] * 1.52587890625e-5f;
        float v = __half2float(__ushort_as_half(V[(size_t)i * C_DIM]));
        P *= a;
        Q = fmaf(a, Q - v, v);
    }
    g_P[idx] = P;
    g_Q[idx] = Q;
}

// pass2 computes its own segment-start h from h0 + prefix chain over (P,Q).
__global__ __launch_bounds__(256) void scan_pass2_kernel(const float* __restrict__ h0,
                                                         float* __restrict__ out,
                                                         float* __restrict__ hs, int write_h) {
    const int idx = blockIdx.x * 256 + threadIdx.x;
    const int ch = idx & (C_DIM - 1);
    const int s = idx >> 13;                 // uniform per block
    float h = h0[ch];
    for (int k = 0; k < s; ++k)              // prefix chain (coalesced, short)
        h = fmaf(g_P[k * C_DIM + ch], h, g_Q[k * C_DIM + ch]);
    if (write_h && s == 0) hs[ch] = h0[ch];  // h[0] row

    const size_t base = (size_t)s * SLEN * C_DIM + ch;
    const unsigned short* __restrict__ A = g_a16 + base;
    const unsigned short* __restrict__ V = g_v16 + base;
#pragma unroll 8
    for (int i = 0; i < SLEN; ++i) {
        float a = (float)A[(size_t)i * C_DIM] * 1.52587890625e-5f;
        float v = __half2float(__ushort_as_half(V[(size_t)i * C_DIM]));
        h = fmaf(a, h - v, v);
        float sil = __fdividef(h, 1.0f + __expf(-h));   // silu(h)
        out[base + (size_t)i * C_DIM] = h * sil;
        if (write_h) hs[base + (size_t)(i + 1) * C_DIM] = h;
    }
}

// ---------------- launch ----------------
extern "C" void kernel_launch(void* const* d_in, const int* in_sizes, int n_in,
                              void* d_out, int out_size) {
    const float* x  = (const float*)d_in[0];
    const float* h0 = (const float*)d_in[1];
    const float* Wa = (const float*)d_in[2];
    const float* ba = (const float*)d_in[3];
    const float* Wv = (const float*)d_in[4];
    const float* bv = (const float*)d_in[5];

    float* out = (float*)d_out;
    const long long out_elems = (long long)T_DIM * C_DIM;
    const long long h_elems = (long long)(T_DIM + 1) * C_DIM;
    const int write_h = (out_size >= (long long)(out_elems + h_elems)) ? 1 : 0;
    float* hs = out + out_elems;

    conv_all_kernel<<<XB + WB, 256>>>(x, Wa, Wv);

    static int configured = 0;
    if (!configured) {
        cudaFuncSetAttribute(gemm_hmma_kernel,
                             cudaFuncAttributeMaxDynamicSharedMemorySize, GSMEM);
        cudaFuncSetAttribute(gemm_hmma_kernel,
                             cudaFuncAttributePreferredSharedMemoryCarveout,
                             cudaSharedmemCarveoutMaxShared);
        configured = 1;
    }
    gemm_hmma_kernel<<<dim3(N_DIM / 128, M_DIM / 128), 256, GSMEM>>>(ba, bv);

    scan_pass1_kernel<<<(SEG * C_DIM) / 256, 256>>>();
    scan_pass2_kernel<<<(SEG * C_DIM) / 256, 256>>>(h0, out, hs, write_h);
}